// round 13
// baseline (speedup 1.0000x reference)
#include <cuda_runtime.h>
#include <cuda_bf16.h>
#include <math.h>

#define BB 64
#define HD 128
#define CC 10
#define SEG 16000               // edge slots per graph
#define NMAX (BB*1000)          // 64000
#define EMAX (BB*SEG)           // 1024000

typedef unsigned long long ull;
typedef __nv_bfloat16 bf16;

// ---------------- scratch (device globals; no allocation) ----------------
__device__ float g_xw[NMAX*HD];
__device__ float g_hc[NMAX*HD];
__device__ __align__(16) bf16 g_hhi[NMAX*HD];
__device__ __align__(16) bf16 g_hlo[NMAX*HD];
__device__ __align__(16) bf16 g_xhi[NMAX*64];
__device__ __align__(16) bf16 g_xlo[NMAX*64];
__device__ __align__(16) bf16 g_whi[6*128*128];   // per layer: [n][k] K-major
__device__ __align__(16) bf16 g_wlo[6*128*128];
__device__ float g_dinv[NMAX];
__device__ int   g_inv[NMAX];           // per-graph local old->new map
__device__ float g_score[NMAX];
__device__ float g_sval[BB*1024];       // sorted top-k scores per graph
__device__ int   g_sidx[BB*1024];       // sorted top-k local indices per graph
__device__ int   g_srcE[2][EMAX];       // graph-local ids, segmented by graph
__device__ int   g_dstE[2][EMAX];
__device__ float g_weE[2][EMAX];
__device__ int   g_rowptr[NMAX];        // absolute CSR start per node
__device__ int   g_rowend[NMAX];        // absolute CSR end per node
__device__ int   g_esrc[EMAX];          // global src ids
__device__ float g_ecoef[EMAX];
__device__ float g_flats[BB*2*HD];
__device__ int   g_gcnt[BB];            // per-graph live edge count

// ---------------- helpers ----------------
__device__ __forceinline__ unsigned smem_u32(const void* p) {
    return (unsigned)__cvta_generic_to_shared(p);
}
#define CPA16(dst, src) asm volatile("cp.async.ca.shared.global [%0], [%1], 16;" :: "r"(dst), "l"(src))

#define LDSM4(r, addr) \
    asm volatile("ldmatrix.sync.aligned.m8n8.x4.shared.b16 {%0,%1,%2,%3}, [%4];" \
        : "=r"((r)[0]), "=r"((r)[1]), "=r"((r)[2]), "=r"((r)[3]) : "r"(addr))

#define MMA16816(c, a, b0, b1) \
    asm volatile("mma.sync.aligned.m16n8k16.row.col.f32.bf16.bf16.f32 " \
        "{%0,%1,%2,%3},{%4,%5,%6,%7},{%8,%9},{%0,%1,%2,%3};" \
        : "+f"((c)[0]), "+f"((c)[1]), "+f"((c)[2]), "+f"((c)[3]) \
        : "r"((a)[0]), "r"((a)[1]), "r"((a)[2]), "r"((a)[3]), "r"(b0), "r"(b1))

__device__ __forceinline__ ull pack4bf(bf16 a0, bf16 a1, bf16 a2, bf16 a3) {
    return (ull)__bfloat16_as_ushort(a0) | ((ull)__bfloat16_as_ushort(a1) << 16)
         | ((ull)__bfloat16_as_ushort(a2) << 32) | ((ull)__bfloat16_as_ushort(a3) << 48);
}

// ---------------- prep kernels ----------------

__global__ void w_prep(const float* __restrict__ w1, const float* __restrict__ w5,
                       bf16* __restrict__ whi, bf16* __restrict__ wlo)
{
    int idx = blockIdx.x * 256 + threadIdx.x;
    if (idx >= 6 * 16384) return;
    int l = idx >> 14, r = idx & 16383;
    float v; int dst;
    if (l == 0) {
        if (r >= 128 * 64) return;
        int n = r >> 6, kk = r & 63;
        v = w1[kk * 128 + n];
        dst = n * 64 + kk;
    } else {
        int n = r >> 7, kk = r & 127;
        v = w5[(size_t)(l - 1) * 16384 + kk * 128 + n];
        dst = l * 16384 + n * 128 + kk;
    }
    bf16 hi = __float2bfloat16(v);
    whi[dst] = hi;
    wlo[dst] = __float2bfloat16(v - __bfloat162float(hi));
}

__global__ void x_prep(const float* __restrict__ x,
                       bf16* __restrict__ xhi, bf16* __restrict__ xlo, int n)
{
    int i = blockIdx.x * 256 + threadIdx.x;
    if (i >= n) return;
    float v = x[i];
    bf16 hi = __float2bfloat16(v);
    xhi[i] = hi;
    xlo[i] = __float2bfloat16(v - __bfloat162float(hi));
}

// ---------------- per-graph edge machinery (one block per graph) ----------------
// compaction bases via block-aggregated warp counts (no same-address smem atomics)
__global__ __launch_bounds__(1024)
void edge_build(const int* __restrict__ pS, const int* __restrict__ pD,
                const float* __restrict__ pW,
                int fixedCnt, int useInv, int subMul, int nPrev, int nCur,
                const int* __restrict__ invG,
                int* __restrict__ srcN, int* __restrict__ dstN, float* __restrict__ weN,
                int* __restrict__ esrc, float* __restrict__ ecoef,
                float* __restrict__ dinvG, int* __restrict__ rowptrG, int* __restrict__ rowendG,
                int* __restrict__ gcnt)
{
    __shared__ int   s_inv[1024];
    __shared__ int   s_indeg[1024];
    __shared__ int   s_cur[1024];
    __shared__ float s_degw[1024];
    __shared__ float s_dinv[1024];
    __shared__ int   s_wcnt[32];
    __shared__ int   s_wbase[32];
    __shared__ int   s_count;

    int b = blockIdx.x;
    int tid = threadIdx.x;
    int lane = tid & 31;
    int wid = tid >> 5;
    unsigned lmask = (1u << lane) - 1u;
    int seg = b * SEG;
    int sub = b * subMul;           // layer0: subtract graph base from global ids

    s_indeg[tid] = 0;
    s_degw[tid] = 0.f;
    if (tid == 0) s_count = 0;
    if (useInv && tid < nPrev) s_inv[tid] = invG[b * nPrev + tid];
    __syncthreads();

    int cnt = useInv ? gcnt[b] : fixedCnt;

    // Phase A: remap + compact + histogram; block-aggregated compaction bases
    int iters = (cnt + 1023) >> 10;
    for (int it = 0; it < iters; it += 2) {
        int e0 = it * 1024 + tid;
        int e1 = e0 + 1024;
        bool in0 = (e0 < cnt), in1 = (it + 1 < iters) && (e1 < cnt);
        int s0 = 0, d0 = 0, s1 = 0, d1 = 0;
        float w0 = 0.f, w1 = 0.f;
        if (in0) { s0 = pS[seg + e0] - sub; d0 = pD[seg + e0] - sub; w0 = pW[seg + e0]; }
        if (in1) { s1 = pS[seg + e1] - sub; d1 = pD[seg + e1] - sub; w1 = pW[seg + e1]; }
        bool a0, a1;
        if (useInv) {
            if (in0) { s0 = s_inv[s0]; d0 = s_inv[d0]; }
            if (in1) { s1 = s_inv[s1]; d1 = s_inv[d1]; }
            a0 = in0 && (s0 >= 0) && (d0 >= 0) && (w0 > 0.f);
            a1 = in1 && (s1 >= 0) && (d1 >= 0) && (w1 > 0.f);
        } else {
            a0 = in0 && (w0 > 0.f);
            a1 = in1 && (w1 > 0.f);
        }
        unsigned m0 = __ballot_sync(0xffffffffu, a0);
        unsigned m1 = __ballot_sync(0xffffffffu, a1);
        int c0 = __popc(m0);
        if (lane == 0) s_wcnt[wid] = c0 + __popc(m1);
        __syncthreads();
        if (wid == 0) {
            int v = s_wcnt[lane];
            int incl = v;
#pragma unroll
            for (int o = 1; o < 32; o <<= 1) {
                int t = __shfl_up_sync(0xffffffffu, incl, o);
                if (lane >= o) incl += t;
            }
            int old = s_count;
            s_wbase[lane] = old + incl - v;
            if (lane == 31) s_count = old + incl;
        }
        __syncthreads();
        int wb = s_wbase[wid];
        if (a0) {
            int pos = wb + __popc(m0 & lmask);
            srcN[seg + pos] = s0; dstN[seg + pos] = d0; weN[seg + pos] = w0;
            atomicAdd(&s_indeg[d0], 1);
            atomicAdd(&s_degw[d0], w0);
        }
        if (a1) {
            int pos = wb + c0 + __popc(m1 & lmask);
            srcN[seg + pos] = s1; dstN[seg + pos] = d1; weN[seg + pos] = w1;
            atomicAdd(&s_indeg[d1], 1);
            atomicAdd(&s_degw[d1], w1);
        }
    }
    __syncthreads();

    // Phase B: block scan of indeg -> CSR bases; dinv; per-node CSR bounds
    {
        int v = s_indeg[tid];
        int incl = v;
#pragma unroll
        for (int o = 1; o < 32; o <<= 1) {
            int t = __shfl_up_sync(0xffffffffu, incl, o);
            if (lane >= o) incl += t;
        }
        if (lane == 31) s_wcnt[wid] = incl;
        __syncthreads();
        if (wid == 0) {
            int sv = s_wcnt[lane];
            int si = sv;
#pragma unroll
            for (int o = 1; o < 32; o <<= 1) {
                int t = __shfl_up_sync(0xffffffffu, si, o);
                if (lane >= o) si += t;
            }
            s_wbase[lane] = si - sv;
        }
        __syncthreads();
        int base = s_wbase[wid] + incl - v;
        s_cur[tid] = base;
        if (tid < nCur) {
            float dv = rsqrtf(1.0f + s_degw[tid]);
            s_dinv[tid] = dv;
            int gn = b * nCur + tid;
            dinvG[gn] = dv;
            rowptrG[gn] = seg + base;
            rowendG[gn] = seg + base + v;
        }
    }
    __syncthreads();

    // Phase C: scatter into CSR slots (smem cursors), 2-edge ILP batches
    int cntN = s_count;
    for (int e = tid; e < cntN; e += 2048) {
        int e2 = e + 1024;
        bool in2 = (e2 < cntN);
        int s0 = srcN[seg + e], d0 = dstN[seg + e];
        float w0 = weN[seg + e];
        int s1 = 0, d1 = 0; float w1 = 0.f;
        if (in2) { s1 = srcN[seg + e2]; d1 = dstN[seg + e2]; w1 = weN[seg + e2]; }
        int p0 = atomicAdd(&s_cur[d0], 1);
        esrc[seg + p0] = b * nCur + s0;
        ecoef[seg + p0] = s_dinv[s0] * s_dinv[d0] * w0;
        if (in2) {
            int p1 = atomicAdd(&s_cur[d1], 1);
            esrc[seg + p1] = b * nCur + s1;
            ecoef[seg + p1] = s_dinv[s1] * s_dinv[d1] * w1;
        }
    }
    if (tid == 0) gcnt[b] = cntN;
}

// ---------------- bf16 split-GEMM via mma.sync (HMMA) ----------------
template<int K>
__global__ __launch_bounds__(256)
void gemm_bf16(const bf16* __restrict__ Ahi, const bf16* __restrict__ Alo,
               const bf16* __restrict__ Whi, const bf16* __restrict__ Wlo,
               float* __restrict__ out)
{
    extern __shared__ __align__(128) char sm[];
    const unsigned smb = smem_u32(sm);
    constexpr int CH = K / 8;
    constexpr int TILEB = 128 * K * 2;
    constexpr unsigned OFF_A = 0;
    constexpr unsigned OFF_W = 2 * TILEB;

    int tid = threadIdx.x;
    int wid = tid >> 5, lane = tid & 31;
    int rowBase = blockIdx.x * 128;

    const bf16* gsrc[4] = { Ahi + (size_t)rowBase * K, Alo + (size_t)rowBase * K, Whi, Wlo };
    const unsigned soff[4] = { OFF_A, OFF_A + TILEB, OFF_W, OFF_W + TILEB };
#pragma unroll
    for (int m = 0; m < 4; m++) {
#pragma unroll
        for (int c = tid; c < 128 * CH; c += 256) {
            int r = c / CH, cc = c % CH;
            CPA16(smb + soff[m] + (unsigned)((r * CH + (cc ^ (r & 7))) * 16),
                  gsrc[m] + (size_t)r * K + cc * 8);
        }
    }
    asm volatile("cp.async.commit_group;");
    asm volatile("cp.async.wait_group 0;");
    __syncthreads();

    int mi = wid & 3, ni = wid >> 2;
    int mbase = mi * 32, nbase = ni * 64;

    float acc[2][8][4];
#pragma unroll
    for (int t = 0; t < 2; t++)
#pragma unroll
        for (int f = 0; f < 8; f++)
#pragma unroll
            for (int j = 0; j < 4; j++) acc[t][f][j] = 0.f;

    int rowA0 = mbase + (lane & 15);
    int rowW0 = nbase + (lane & 7) + ((lane >> 4) << 3);
    int kselA = (lane >> 4) & 1;
    int kselW = (lane >> 3) & 1;

#pragma unroll
    for (int s = 0; s < K / 16; s++) {
        unsigned aHi[2][4], aLo[2][4];
#pragma unroll
        for (int t = 0; t < 2; t++) {
            int row = rowA0 + t * 16;
            unsigned addr = smb + OFF_A + (unsigned)((row * CH + ((2 * s + kselA) ^ (row & 7))) * 16);
            LDSM4(aHi[t], addr);
            LDSM4(aLo[t], addr + TILEB);
        }
#pragma unroll
        for (int u = 0; u < 4; u++) {
            int row = rowW0 + u * 16;
            unsigned addr = smb + OFF_W + (unsigned)((row * CH + ((2 * s + kselW) ^ (row & 7))) * 16);
            unsigned bHi[4], bLo[4];
            LDSM4(bHi, addr);
            LDSM4(bLo, addr + TILEB);
#pragma unroll
            for (int t = 0; t < 2; t++) {
                MMA16816(acc[t][2 * u],     aHi[t], bHi[0], bHi[1]);
                MMA16816(acc[t][2 * u + 1], aHi[t], bHi[2], bHi[3]);
                MMA16816(acc[t][2 * u],     aHi[t], bLo[0], bLo[1]);
                MMA16816(acc[t][2 * u + 1], aHi[t], bLo[2], bLo[3]);
                MMA16816(acc[t][2 * u],     aLo[t], bHi[0], bHi[1]);
                MMA16816(acc[t][2 * u + 1], aLo[t], bHi[2], bHi[3]);
            }
        }
    }

    int g = lane >> 2, tg = lane & 3;
#pragma unroll
    for (int t = 0; t < 2; t++) {
        int row0 = rowBase + mbase + t * 16 + g;
#pragma unroll
        for (int f = 0; f < 8; f++) {
            int col = nbase + f * 8 + tg * 2;
            *(float2*)(out + (size_t)row0 * 128 + col) = make_float2(acc[t][f][0], acc[t][f][1]);
            *(float2*)(out + (size_t)(row0 + 8) * 128 + col) = make_float2(acc[t][f][2], acc[t][f][3]);
        }
    }
}

// ---------------- CSR gather + BN + ReLU + score: 2 blocks per graph ----------------
__global__ __launch_bounds__(1024)
void gcn_gather(const float* __restrict__ xw, const int* __restrict__ rowptr,
                const int* __restrict__ rowend,
                const int* __restrict__ esrc, const float* __restrict__ ecoef,
                const float* __restrict__ dinv,
                const float* __restrict__ bias, const float* __restrict__ bng,
                const float* __restrict__ bnb, const float* __restrict__ bnm,
                const float* __restrict__ bnv, const float* __restrict__ pw,
                float* __restrict__ hc, float* __restrict__ score, int n)
{
    int b = blockIdx.x >> 1;
    int half = blockIdx.x & 1;
    int warp = threadIdx.x >> 5;
    int l = threadIdx.x & 31;

    float4 bb = ((const float4*)bias)[l];
    float4 g  = ((const float4*)bng)[l];
    float4 be = ((const float4*)bnb)[l];
    float4 m  = ((const float4*)bnm)[l];
    float4 vv = ((const float4*)bnv)[l];
    float4 p  = ((const float4*)pw)[l];
    float4 bnscale = make_float4(g.x * rsqrtf(vv.x + 1e-5f), g.y * rsqrtf(vv.y + 1e-5f),
                                 g.z * rsqrtf(vv.z + 1e-5f), g.w * rsqrtf(vv.w + 1e-5f));

    for (int nn = half * 32 + warp; nn < n; nn += 64) {
        int node = b * n + nn;
        float di = dinv[node];
        float sc = di * di;
        float4 a = ((const float4*)(xw + (size_t)node * 128))[l];
        float4 ac0 = make_float4(a.x * sc, a.y * sc, a.z * sc, a.w * sc);
        float4 ac1 = make_float4(0.f, 0.f, 0.f, 0.f);
        float4 ac2 = make_float4(0.f, 0.f, 0.f, 0.f);
        float4 ac3 = make_float4(0.f, 0.f, 0.f, 0.f);
        int e0 = rowptr[node], e1 = rowend[node];
        int e = e0;
        for (; e + 4 <= e1; e += 4) {
            int s0 = esrc[e], s1 = esrc[e + 1], s2 = esrc[e + 2], s3 = esrc[e + 3];
            float c0 = ecoef[e], c1 = ecoef[e + 1], c2 = ecoef[e + 2], c3 = ecoef[e + 3];
            float4 v0 = ((const float4*)(xw + (size_t)s0 * 128))[l];
            float4 v1 = ((const float4*)(xw + (size_t)s1 * 128))[l];
            float4 v2 = ((const float4*)(xw + (size_t)s2 * 128))[l];
            float4 v3 = ((const float4*)(xw + (size_t)s3 * 128))[l];
            ac0.x = fmaf(c0, v0.x, ac0.x); ac0.y = fmaf(c0, v0.y, ac0.y);
            ac0.z = fmaf(c0, v0.z, ac0.z); ac0.w = fmaf(c0, v0.w, ac0.w);
            ac1.x = fmaf(c1, v1.x, ac1.x); ac1.y = fmaf(c1, v1.y, ac1.y);
            ac1.z = fmaf(c1, v1.z, ac1.z); ac1.w = fmaf(c1, v1.w, ac1.w);
            ac2.x = fmaf(c2, v2.x, ac2.x); ac2.y = fmaf(c2, v2.y, ac2.y);
            ac2.z = fmaf(c2, v2.z, ac2.z); ac2.w = fmaf(c2, v2.w, ac2.w);
            ac3.x = fmaf(c3, v3.x, ac3.x); ac3.y = fmaf(c3, v3.y, ac3.y);
            ac3.z = fmaf(c3, v3.z, ac3.z); ac3.w = fmaf(c3, v3.w, ac3.w);
        }
        for (; e < e1; e++) {
            int s = esrc[e];
            float c = ecoef[e];
            float4 v = ((const float4*)(xw + (size_t)s * 128))[l];
            ac0.x = fmaf(c, v.x, ac0.x); ac0.y = fmaf(c, v.y, ac0.y);
            ac0.z = fmaf(c, v.z, ac0.z); ac0.w = fmaf(c, v.w, ac0.w);
        }
        ac0.x += ac1.x + ac2.x + ac3.x;
        ac0.y += ac1.y + ac2.y + ac3.y;
        ac0.z += ac1.z + ac2.z + ac3.z;
        ac0.w += ac1.w + ac2.w + ac3.w;
        float4 o;
        o.x = fmaxf((ac0.x + bb.x - m.x) * bnscale.x + be.x, 0.f);
        o.y = fmaxf((ac0.y + bb.y - m.y) * bnscale.y + be.y, 0.f);
        o.z = fmaxf((ac0.z + bb.z - m.z) * bnscale.z + be.z, 0.f);
        o.w = fmaxf((ac0.w + bb.w - m.w) * bnscale.w + be.w, 0.f);
        ((float4*)(hc + (size_t)node * 128))[l] = o;
        float dot = o.x * p.x + o.y * p.y + o.z * p.z + o.w * p.w;
        float p2  = p.x * p.x + p.y * p.y + p.z * p.z + p.w * p.w;
#pragma unroll
        for (int off = 16; off; off >>= 1) {
            dot += __shfl_xor_sync(0xffffffffu, dot, off);
            p2  += __shfl_xor_sync(0xffffffffu, p2, off);
        }
        if (l == 0) score[node] = tanhf(dot * rsqrtf(p2));
    }
}

// bitonic sort (SL = 512 or 1024 elements) + inv map + export sorted top-k
__global__ __launch_bounds__(1024)
void sort_inv(const float* __restrict__ score, float* __restrict__ svals,
              int* __restrict__ sidxg, int* __restrict__ inv, int n, int k, int SL)
{
    __shared__ float skey[1024];
    __shared__ int   sidx[1024];
    int b = blockIdx.x;
    int tid = threadIdx.x;

    if (tid < SL) {
        skey[tid] = (tid < n) ? score[b * n + tid] : -3.402823466e38f;
        sidx[tid] = tid;
    }
    __syncthreads();

    for (int kk = 2; kk <= SL; kk <<= 1) {
        for (int j = kk >> 1; j > 0; j >>= 1) {
            if (tid < (SL >> 1)) {
                int i = ((tid & ~(j - 1)) << 1) | (tid & (j - 1));
                int ixj = i | j;
                float ka = skey[i], kb = skey[ixj];
                int ia = sidx[i], ib = sidx[ixj];
                bool up = ((i & kk) == 0);
                bool sw = up ? ((ka < kb) || (ka == kb && ia > ib))
                             : ((ka > kb) || (ka == kb && ia < ib));
                if (sw) { skey[i] = kb; skey[ixj] = ka; sidx[i] = ib; sidx[ixj] = ia; }
            }
            __syncthreads();
        }
    }

    if (tid < n) inv[b * n + tid] = -1;
    __syncthreads();
    if (tid < k) {
        inv[b * n + sidx[tid]] = tid;
        svals[b * 1024 + tid] = skey[tid];
        sidxg[b * 1024 + tid] = sidx[tid];
    }
}

// pool: gather selected hc rows, scale, bf16 hi/lo split + mean/max flats
__global__ __launch_bounds__(1024)
void pool_kernel(const float* __restrict__ hc, const float* __restrict__ svals,
                 const int* __restrict__ sidxg,
                 bf16* __restrict__ hhi, bf16* __restrict__ hlo,
                 float* __restrict__ flats, int n, int k, int accum)
{
    __shared__ float4 ssum[32][32];
    __shared__ float4 smax[32][32];
    int b = blockIdx.x;
    int tid = threadIdx.x;
    int w = tid >> 5, l = tid & 31;

    float4 sum = make_float4(0.f, 0.f, 0.f, 0.f);
    float4 mx  = make_float4(-3.402823466e38f, -3.402823466e38f, -3.402823466e38f, -3.402823466e38f);
    for (int j = w; j < k; j += 32) {
        int p = b * n + sidxg[b * 1024 + j];
        float v = svals[b * 1024 + j];
        float4 hv = ((const float4*)(hc + (size_t)p * 128))[l];
        hv.x *= v; hv.y *= v; hv.z *= v; hv.w *= v;
        bf16 a0 = __float2bfloat16(hv.x), a1 = __float2bfloat16(hv.y);
        bf16 a2 = __float2bfloat16(hv.z), a3 = __float2bfloat16(hv.w);
        bf16 b0 = __float2bfloat16(hv.x - __bfloat162float(a0));
        bf16 b1 = __float2bfloat16(hv.y - __bfloat162float(a1));
        bf16 b2 = __float2bfloat16(hv.z - __bfloat162float(a2));
        bf16 b3 = __float2bfloat16(hv.w - __bfloat162float(a3));
        size_t rbase = (size_t)(b * k + j) * 128 + l * 4;
        *(ull*)(hhi + rbase) = pack4bf(a0, a1, a2, a3);
        *(ull*)(hlo + rbase) = pack4bf(b0, b1, b2, b3);
        sum.x += hv.x; sum.y += hv.y; sum.z += hv.z; sum.w += hv.w;
        mx.x = fmaxf(mx.x, hv.x); mx.y = fmaxf(mx.y, hv.y);
        mx.z = fmaxf(mx.z, hv.z); mx.w = fmaxf(mx.w, hv.w);
    }
    ssum[w][l] = sum; smax[w][l] = mx;
    __syncthreads();
    if (w == 0) {
#pragma unroll
        for (int q = 1; q < 32; q++) {
            float4 s2 = ssum[q][l], m2 = smax[q][l];
            sum.x += s2.x; sum.y += s2.y; sum.z += s2.z; sum.w += s2.w;
            mx.x = fmaxf(mx.x, m2.x); mx.y = fmaxf(mx.y, m2.y);
            mx.z = fmaxf(mx.z, m2.z); mx.w = fmaxf(mx.w, m2.w);
        }
        float kin = (float)k;
        float* f1 = flats + b * 256 + l * 4;
        float* f2 = flats + b * 256 + 128 + l * 4;
        if (accum) {
            f1[0] += sum.x / kin; f1[1] += sum.y / kin; f1[2] += sum.z / kin; f1[3] += sum.w / kin;
            f2[0] += mx.x; f2[1] += mx.y; f2[2] += mx.z; f2[3] += mx.w;
        } else {
            f1[0] = sum.x / kin; f1[1] = sum.y / kin; f1[2] = sum.z / kin; f1[3] = sum.w / kin;
            f2[0] = mx.x; f2[1] = mx.y; f2[2] = mx.z; f2[3] = mx.w;
        }
    }
}

__global__ __launch_bounds__(512)
void mlp_kernel(const float* __restrict__ flats, const float* __restrict__ d1w,
                const float* __restrict__ d1b, const float* __restrict__ d2w,
                const float* __restrict__ d2b, float* __restrict__ out)
{
    __shared__ float f[256];
    __shared__ float hd[512];
    int b = blockIdx.x, t = threadIdx.x;
    if (t < 256) f[t] = flats[b * 256 + t];
    __syncthreads();
    float acc = d1b[t];
#pragma unroll 8
    for (int i = 0; i < 256; i++) acc = fmaf(f[i], d1w[i * 512 + t], acc);
    hd[t] = fmaxf(acc, 0.f);
    __syncthreads();
    if (t < CC) {
        float o = d2b[t];
#pragma unroll 8
        for (int i = 0; i < 512; i++) o = fmaf(hd[i], d2w[i * CC + t], o);
        out[b * CC + t] = o;
    }
}

// ---------------- host launcher ----------------
extern "C" void kernel_launch(void* const* d_in, const int* in_sizes, int n_in,
                              void* d_out, int out_size)
{
    const float* x       = (const float*)d_in[0];
    const int*   ei      = (const int*)d_in[1];
    const float* ew      = (const float*)d_in[3];
    const float* conv1_w = (const float*)d_in[4];
    const float* conv_w  = (const float*)d_in[5];
    const float* conv_b  = (const float*)d_in[6];
    const float* bn_g    = (const float*)d_in[7];
    const float* bn_be   = (const float*)d_in[8];
    const float* bn_m    = (const float*)d_in[9];
    const float* bn_v    = (const float*)d_in[10];
    const float* pool_w  = (const float*)d_in[11];
    const float* d1w     = (const float*)d_in[12];
    const float* d1b     = (const float*)d_in[13];
    const float* d2w     = (const float*)d_in[14];
    const float* d2b     = (const float*)d_in[15];
    int E = in_sizes[3];

    float *xw, *hc, *score, *sval, *ecoef, *flats, *dinv;
    float *weE[2];
    int *rowptr, *rowend, *esrc, *inv, *gcnt, *sidxg;
    int *srcE[2], *dstE[2];
    bf16 *xhi, *xlo, *hhi, *hlo, *whi, *wlo;
    cudaGetSymbolAddress((void**)&xw,     g_xw);
    cudaGetSymbolAddress((void**)&hc,     g_hc);
    cudaGetSymbolAddress((void**)&score,  g_score);
    cudaGetSymbolAddress((void**)&sval,   g_sval);
    cudaGetSymbolAddress((void**)&sidxg,  g_sidx);
    cudaGetSymbolAddress((void**)&rowptr, g_rowptr);
    cudaGetSymbolAddress((void**)&rowend, g_rowend);
    cudaGetSymbolAddress((void**)&esrc,   g_esrc);
    cudaGetSymbolAddress((void**)&ecoef,  g_ecoef);
    cudaGetSymbolAddress((void**)&flats,  g_flats);
    cudaGetSymbolAddress((void**)&dinv,   g_dinv);
    cudaGetSymbolAddress((void**)&inv,    g_inv);
    cudaGetSymbolAddress((void**)&gcnt,   g_gcnt);
    cudaGetSymbolAddress((void**)&xhi,    g_xhi);
    cudaGetSymbolAddress((void**)&xlo,    g_xlo);
    cudaGetSymbolAddress((void**)&hhi,    g_hhi);
    cudaGetSymbolAddress((void**)&hlo,    g_hlo);
    cudaGetSymbolAddress((void**)&whi,    g_whi);
    cudaGetSymbolAddress((void**)&wlo,    g_wlo);
    {
        float* p; int* q;
        cudaGetSymbolAddress((void**)&q, g_srcE);   srcE[0] = q; srcE[1] = q + EMAX;
        cudaGetSymbolAddress((void**)&q, g_dstE);   dstE[0] = q; dstE[1] = q + EMAX;
        cudaGetSymbolAddress((void**)&p, g_weE);    weE[0]  = p; weE[1]  = p + EMAX;
    }

    const int ns[6] = {1000, 800, 640, 512, 410, 328};
    const int ks[6] = {800, 640, 512, 410, 328, 263};
    const int sl[6] = {1024, 1024, 1024, 512, 512, 512};
    const int SMEM_G64  = 4 * 128 * 64 * 2;    // 65536
    const int SMEM_G128 = 4 * 128 * 128 * 2;   // 131072

    cudaFuncSetAttribute(gemm_bf16<64>,  cudaFuncAttributeMaxDynamicSharedMemorySize, SMEM_G64);
    cudaFuncSetAttribute(gemm_bf16<128>, cudaFuncAttributeMaxDynamicSharedMemorySize, SMEM_G128);

    // static stream + event pool: created ONCE, reused every call (no per-call allocation)
    static cudaStream_t s1 = 0;
    static cudaEvent_t evp[16];
    static int inited = 0;
    if (!inited) {
        cudaStreamCreateWithFlags(&s1, cudaStreamNonBlocking);
        for (int i = 0; i < 16; i++)
            cudaEventCreateWithFlags(&evp[i], cudaEventDisableTiming);
        inited = 1;
    }
    cudaStream_t s0 = (cudaStream_t)0;
    int evc = 0;

    #define FORK_S1() do { cudaEvent_t e_ = evp[evc++]; \
        cudaEventRecord(e_, s0); cudaStreamWaitEvent(s1, e_, 0); } while (0)
    #define JOIN_S0() do { cudaEvent_t e_ = evp[evc++]; \
        cudaEventRecord(e_, s1); cudaStreamWaitEvent(s0, e_, 0); } while (0)

    // ---- prologue: edge build (layer0) on s0 ∥ prep + gemm0 on s1 ----
    FORK_S1();
    w_prep<<<(6 * 16384 + 255) / 256, 256, 0, s1>>>(conv1_w, conv_w, whi, wlo);
    x_prep<<<(NMAX * 64 + 255) / 256, 256, 0, s1>>>(x, xhi, xlo, NMAX * 64);
    gemm_bf16<64><<<BB * ns[0] / 128, 256, SMEM_G64, s1>>>(xhi, xlo, whi, wlo, xw);

    edge_build<<<BB, 1024, 0, s0>>>(ei, ei + E, ew, SEG, 0, 1000, 0, ns[0], (const int*)0,
                                    srcE[0], dstE[0], weE[0], esrc, ecoef,
                                    dinv, rowptr, rowend, gcnt);
    JOIN_S0();

    for (int i = 0; i < 6; i++) {
        int n = ns[i], k = ks[i];
        int cur = i & 1, nxt = cur ^ 1;

        gcn_gather<<<2 * BB, 1024, 0, s0>>>(xw, rowptr, rowend, esrc, ecoef, dinv,
                                            conv_b + i * 128, bn_g + i * 128, bn_be + i * 128,
                                            bn_m + i * 128, bn_v + i * 128, pool_w + i * 128,
                                            hc, score, n);

        sort_inv<<<BB, 1024, 0, s0>>>(score, sval, sidxg, inv, n, k, sl[i]);

        if (i < 5) {
            // edge_build(i+1) depends only on inv — overlap with pool + gemm(i+1)
            FORK_S1();
            edge_build<<<BB, 1024, 0, s1>>>(srcE[cur], dstE[cur], weE[cur], 0, 1, 0,
                                            n, ns[i + 1], inv,
                                            srcE[nxt], dstE[nxt], weE[nxt], esrc, ecoef,
                                            dinv, rowptr, rowend, gcnt);
        }

        pool_kernel<<<BB, 1024, 0, s0>>>(hc, sval, sidxg, hhi, hlo, flats, n, k, i > 0);

        if (i < 5) {
            gemm_bf16<128><<<BB * ks[i] / 128, 256, SMEM_G128, s0>>>(hhi, hlo,
                whi + (size_t)(i + 1) * 16384, wlo + (size_t)(i + 1) * 16384, xw);
            JOIN_S0();   // wait for edge_build(i+1)
        }
    }

    mlp_kernel<<<BB, 512, 0, s0>>>(flats, d1w, d1b, d2w, d2b, (float*)d_out);

    #undef FORK_S1
    #undef JOIN_S0
}

// round 14
// speedup vs baseline: 1.0486x; 1.0486x over previous
#include <cuda_runtime.h>
#include <cuda_bf16.h>
#include <math.h>

#define BB 64
#define HD 128
#define CC 10
#define SEG 16000               // edge slots per graph
#define NMAX (BB*1000)          // 64000
#define EMAX (BB*SEG)           // 1024000

typedef unsigned long long ull;
typedef __nv_bfloat16 bf16;

// ---------------- scratch (device globals; no allocation) ----------------
__device__ float g_xw[NMAX*HD];
__device__ float g_hc[NMAX*HD];
__device__ __align__(16) bf16 g_hhi[NMAX*HD];
__device__ __align__(16) bf16 g_hlo[NMAX*HD];
__device__ __align__(16) bf16 g_xhi[NMAX*64];
__device__ __align__(16) bf16 g_xlo[NMAX*64];
__device__ __align__(16) bf16 g_whi[6*128*128];   // per layer: [n][k] K-major
__device__ __align__(16) bf16 g_wlo[6*128*128];
__device__ float g_dinv[NMAX];
__device__ int   g_inv[NMAX];           // per-graph local old->new map
__device__ float g_score[NMAX];
__device__ float g_sval[BB*1024];       // sorted top-k scores per graph
__device__ int   g_sidx[BB*1024];       // sorted top-k local indices per graph
__device__ int   g_srcE[2][EMAX];       // graph-local ids, segmented by graph
__device__ int   g_dstE[2][EMAX];
__device__ float g_weE[2][EMAX];
__device__ int   g_rowptr[NMAX];        // absolute CSR start per node
__device__ int   g_rowend[NMAX];        // absolute CSR end per node
__device__ int   g_esrc[EMAX];          // global src ids
__device__ float g_ecoef[EMAX];
__device__ float g_flats[BB*2*HD];
__device__ int   g_gcnt[BB];            // per-graph live edge count

// ---------------- helpers ----------------
__device__ __forceinline__ unsigned smem_u32(const void* p) {
    return (unsigned)__cvta_generic_to_shared(p);
}
#define CPA16(dst, src) asm volatile("cp.async.ca.shared.global [%0], [%1], 16;" :: "r"(dst), "l"(src))

#define LDSM4(r, addr) \
    asm volatile("ldmatrix.sync.aligned.m8n8.x4.shared.b16 {%0,%1,%2,%3}, [%4];" \
        : "=r"((r)[0]), "=r"((r)[1]), "=r"((r)[2]), "=r"((r)[3]) : "r"(addr))

#define MMA16816(c, a, b0, b1) \
    asm volatile("mma.sync.aligned.m16n8k16.row.col.f32.bf16.bf16.f32 " \
        "{%0,%1,%2,%3},{%4,%5,%6,%7},{%8,%9},{%0,%1,%2,%3};" \
        : "+f"((c)[0]), "+f"((c)[1]), "+f"((c)[2]), "+f"((c)[3]) \
        : "r"((a)[0]), "r"((a)[1]), "r"((a)[2]), "r"((a)[3]), "r"(b0), "r"(b1))

__device__ __forceinline__ ull pack4bf(bf16 a0, bf16 a1, bf16 a2, bf16 a3) {
    return (ull)__bfloat16_as_ushort(a0) | ((ull)__bfloat16_as_ushort(a1) << 16)
         | ((ull)__bfloat16_as_ushort(a2) << 32) | ((ull)__bfloat16_as_ushort(a3) << 48);
}

// ---------------- prep kernels ----------------

__global__ void w_prep(const float* __restrict__ w1, const float* __restrict__ w5,
                       bf16* __restrict__ whi, bf16* __restrict__ wlo)
{
    int idx = blockIdx.x * 256 + threadIdx.x;
    if (idx >= 6 * 16384) return;
    int l = idx >> 14, r = idx & 16383;
    float v; int dst;
    if (l == 0) {
        if (r >= 128 * 64) return;
        int n = r >> 6, kk = r & 63;
        v = w1[kk * 128 + n];
        dst = n * 64 + kk;
    } else {
        int n = r >> 7, kk = r & 127;
        v = w5[(size_t)(l - 1) * 16384 + kk * 128 + n];
        dst = l * 16384 + n * 128 + kk;
    }
    bf16 hi = __float2bfloat16(v);
    whi[dst] = hi;
    wlo[dst] = __float2bfloat16(v - __bfloat162float(hi));
}

__global__ void x_prep(const float* __restrict__ x,
                       bf16* __restrict__ xhi, bf16* __restrict__ xlo, int n)
{
    int i = blockIdx.x * 256 + threadIdx.x;
    if (i >= n) return;
    float v = x[i];
    bf16 hi = __float2bfloat16(v);
    xhi[i] = hi;
    xlo[i] = __float2bfloat16(v - __bfloat162float(hi));
}

// ---------------- per-graph edge machinery (one block per graph) ----------------
// R11 version: ballot compact with per-warp-leader smem atomic (measured best)
__global__ __launch_bounds__(1024)
void edge_build(const int* __restrict__ pS, const int* __restrict__ pD,
                const float* __restrict__ pW,
                int fixedCnt, int useInv, int subMul, int nPrev, int nCur,
                const int* __restrict__ invG,
                int* __restrict__ srcN, int* __restrict__ dstN, float* __restrict__ weN,
                int* __restrict__ esrc, float* __restrict__ ecoef,
                float* __restrict__ dinvG, int* __restrict__ rowptrG, int* __restrict__ rowendG,
                int* __restrict__ gcnt)
{
    __shared__ int   s_inv[1024];
    __shared__ int   s_indeg[1024];
    __shared__ int   s_cur[1024];
    __shared__ float s_degw[1024];
    __shared__ float s_dinv[1024];
    __shared__ int   s_wsum[32];
    __shared__ int   s_woff[32];
    __shared__ int   s_count;

    int b = blockIdx.x;
    int tid = threadIdx.x;
    int lane = tid & 31;
    int seg = b * SEG;
    int sub = b * subMul;           // layer0: subtract graph base from global ids

    s_indeg[tid] = 0;
    s_degw[tid] = 0.f;
    if (tid == 0) s_count = 0;
    if (useInv && tid < nPrev) s_inv[tid] = invG[b * nPrev + tid];
    __syncthreads();

    int cnt = useInv ? gcnt[b] : fixedCnt;

    // Phase A: remap + compact + histogram (2-edge ILP batches)
    int iters = (cnt + 1023) >> 10;
    for (int it = 0; it < iters; it += 2) {
        int e0 = it * 1024 + tid;
        int e1 = e0 + 1024;
        bool in0 = (e0 < cnt), in1 = (it + 1 < iters) && (e1 < cnt);
        int s0 = 0, d0 = 0, s1 = 0, d1 = 0;
        float w0 = 0.f, w1 = 0.f;
        if (in0) { s0 = pS[seg + e0] - sub; d0 = pD[seg + e0] - sub; w0 = pW[seg + e0]; }
        if (in1) { s1 = pS[seg + e1] - sub; d1 = pD[seg + e1] - sub; w1 = pW[seg + e1]; }
        bool a0, a1;
        if (useInv) {
            if (in0) { s0 = s_inv[s0]; d0 = s_inv[d0]; }
            if (in1) { s1 = s_inv[s1]; d1 = s_inv[d1]; }
            a0 = in0 && (s0 >= 0) && (d0 >= 0) && (w0 > 0.f);
            a1 = in1 && (s1 >= 0) && (d1 >= 0) && (w1 > 0.f);
        } else {
            a0 = in0 && (w0 > 0.f);
            a1 = in1 && (w1 > 0.f);
        }
#pragma unroll
        for (int r = 0; r < 2; r++) {
            bool alive = r ? a1 : a0;
            int s = r ? s1 : s0, d = r ? d1 : d0;
            float w = r ? w1 : w0;
            unsigned m = __ballot_sync(0xffffffffu, alive);
            if (m) {
                int leader = __ffs(m) - 1;
                int base = 0;
                if (lane == leader) base = atomicAdd(&s_count, __popc(m));
                base = __shfl_sync(0xffffffffu, base, leader);
                if (alive) {
                    int pos = base + __popc(m & ((1u << lane) - 1));
                    srcN[seg + pos] = s;
                    dstN[seg + pos] = d;
                    weN[seg + pos] = w;
                    atomicAdd(&s_indeg[d], 1);
                    atomicAdd(&s_degw[d], w);
                }
            }
        }
    }
    __syncthreads();

    // Phase B: block scan of indeg -> CSR bases; dinv; per-node CSR bounds
    {
        int wid = tid >> 5;
        int v = s_indeg[tid];
        int incl = v;
#pragma unroll
        for (int o = 1; o < 32; o <<= 1) {
            int t = __shfl_up_sync(0xffffffffu, incl, o);
            if (lane >= o) incl += t;
        }
        if (lane == 31) s_wsum[wid] = incl;
        __syncthreads();
        if (wid == 0) {
            int sv = s_wsum[lane];
            int si = sv;
#pragma unroll
            for (int o = 1; o < 32; o <<= 1) {
                int t = __shfl_up_sync(0xffffffffu, si, o);
                if (lane >= o) si += t;
            }
            s_woff[lane] = si - sv;
        }
        __syncthreads();
        int base = s_woff[tid >> 5] + incl - v;
        s_cur[tid] = base;
        if (tid < nCur) {
            float dv = rsqrtf(1.0f + s_degw[tid]);
            s_dinv[tid] = dv;
            int gn = b * nCur + tid;
            dinvG[gn] = dv;
            rowptrG[gn] = seg + base;
            rowendG[gn] = seg + base + v;
        }
    }
    __syncthreads();

    // Phase C: scatter into CSR slots (smem cursors), 2-edge ILP batches
    int cntN = s_count;
    for (int e = tid; e < cntN; e += 2048) {
        int e2 = e + 1024;
        bool in2 = (e2 < cntN);
        int s0 = srcN[seg + e], d0 = dstN[seg + e];
        float w0 = weN[seg + e];
        int s1 = 0, d1 = 0; float w1 = 0.f;
        if (in2) { s1 = srcN[seg + e2]; d1 = dstN[seg + e2]; w1 = weN[seg + e2]; }
        int p0 = atomicAdd(&s_cur[d0], 1);
        esrc[seg + p0] = b * nCur + s0;
        ecoef[seg + p0] = s_dinv[s0] * s_dinv[d0] * w0;
        if (in2) {
            int p1 = atomicAdd(&s_cur[d1], 1);
            esrc[seg + p1] = b * nCur + s1;
            ecoef[seg + p1] = s_dinv[s1] * s_dinv[d1] * w1;
        }
    }
    if (tid == 0) gcnt[b] = cntN;
}

// ---------------- bf16 split-GEMM via mma.sync (HMMA) ----------------
template<int K>
__global__ __launch_bounds__(256)
void gemm_bf16(const bf16* __restrict__ Ahi, const bf16* __restrict__ Alo,
               const bf16* __restrict__ Whi, const bf16* __restrict__ Wlo,
               float* __restrict__ out)
{
    extern __shared__ __align__(128) char sm[];
    const unsigned smb = smem_u32(sm);
    constexpr int CH = K / 8;
    constexpr int TILEB = 128 * K * 2;
    constexpr unsigned OFF_A = 0;
    constexpr unsigned OFF_W = 2 * TILEB;

    int tid = threadIdx.x;
    int wid = tid >> 5, lane = tid & 31;
    int rowBase = blockIdx.x * 128;

    const bf16* gsrc[4] = { Ahi + (size_t)rowBase * K, Alo + (size_t)rowBase * K, Whi, Wlo };
    const unsigned soff[4] = { OFF_A, OFF_A + TILEB, OFF_W, OFF_W + TILEB };
#pragma unroll
    for (int m = 0; m < 4; m++) {
#pragma unroll
        for (int c = tid; c < 128 * CH; c += 256) {
            int r = c / CH, cc = c % CH;
            CPA16(smb + soff[m] + (unsigned)((r * CH + (cc ^ (r & 7))) * 16),
                  gsrc[m] + (size_t)r * K + cc * 8);
        }
    }
    asm volatile("cp.async.commit_group;");
    asm volatile("cp.async.wait_group 0;");
    __syncthreads();

    int mi = wid & 3, ni = wid >> 2;
    int mbase = mi * 32, nbase = ni * 64;

    float acc[2][8][4];
#pragma unroll
    for (int t = 0; t < 2; t++)
#pragma unroll
        for (int f = 0; f < 8; f++)
#pragma unroll
            for (int j = 0; j < 4; j++) acc[t][f][j] = 0.f;

    int rowA0 = mbase + (lane & 15);
    int rowW0 = nbase + (lane & 7) + ((lane >> 4) << 3);
    int kselA = (lane >> 4) & 1;
    int kselW = (lane >> 3) & 1;

#pragma unroll
    for (int s = 0; s < K / 16; s++) {
        unsigned aHi[2][4], aLo[2][4];
#pragma unroll
        for (int t = 0; t < 2; t++) {
            int row = rowA0 + t * 16;
            unsigned addr = smb + OFF_A + (unsigned)((row * CH + ((2 * s + kselA) ^ (row & 7))) * 16);
            LDSM4(aHi[t], addr);
            LDSM4(aLo[t], addr + TILEB);
        }
#pragma unroll
        for (int u = 0; u < 4; u++) {
            int row = rowW0 + u * 16;
            unsigned addr = smb + OFF_W + (unsigned)((row * CH + ((2 * s + kselW) ^ (row & 7))) * 16);
            unsigned bHi[4], bLo[4];
            LDSM4(bHi, addr);
            LDSM4(bLo, addr + TILEB);
#pragma unroll
            for (int t = 0; t < 2; t++) {
                MMA16816(acc[t][2 * u],     aHi[t], bHi[0], bHi[1]);
                MMA16816(acc[t][2 * u + 1], aHi[t], bHi[2], bHi[3]);
                MMA16816(acc[t][2 * u],     aHi[t], bLo[0], bLo[1]);
                MMA16816(acc[t][2 * u + 1], aHi[t], bLo[2], bLo[3]);
                MMA16816(acc[t][2 * u],     aLo[t], bHi[0], bHi[1]);
                MMA16816(acc[t][2 * u + 1], aLo[t], bHi[2], bHi[3]);
            }
        }
    }

    int g = lane >> 2, tg = lane & 3;
#pragma unroll
    for (int t = 0; t < 2; t++) {
        int row0 = rowBase + mbase + t * 16 + g;
#pragma unroll
        for (int f = 0; f < 8; f++) {
            int col = nbase + f * 8 + tg * 2;
            *(float2*)(out + (size_t)row0 * 128 + col) = make_float2(acc[t][f][0], acc[t][f][1]);
            *(float2*)(out + (size_t)(row0 + 8) * 128 + col) = make_float2(acc[t][f][2], acc[t][f][3]);
        }
    }
}

// ---------------- CSR gather + BN + ReLU + score: 2 blocks per graph ----------------
__global__ __launch_bounds__(1024)
void gcn_gather(const float* __restrict__ xw, const int* __restrict__ rowptr,
                const int* __restrict__ rowend,
                const int* __restrict__ esrc, const float* __restrict__ ecoef,
                const float* __restrict__ dinv,
                const float* __restrict__ bias, const float* __restrict__ bng,
                const float* __restrict__ bnb, const float* __restrict__ bnm,
                const float* __restrict__ bnv, const float* __restrict__ pw,
                float* __restrict__ hc, float* __restrict__ score, int n)
{
    int b = blockIdx.x >> 1;
    int half = blockIdx.x & 1;
    int warp = threadIdx.x >> 5;
    int l = threadIdx.x & 31;

    float4 bb = ((const float4*)bias)[l];
    float4 g  = ((const float4*)bng)[l];
    float4 be = ((const float4*)bnb)[l];
    float4 m  = ((const float4*)bnm)[l];
    float4 vv = ((const float4*)bnv)[l];
    float4 p  = ((const float4*)pw)[l];
    float4 bnscale = make_float4(g.x * rsqrtf(vv.x + 1e-5f), g.y * rsqrtf(vv.y + 1e-5f),
                                 g.z * rsqrtf(vv.z + 1e-5f), g.w * rsqrtf(vv.w + 1e-5f));
    // loop-invariant: pool-weight norm (was recomputed per node)
    float p2 = p.x * p.x + p.y * p.y + p.z * p.z + p.w * p.w;
#pragma unroll
    for (int off = 16; off; off >>= 1) p2 += __shfl_xor_sync(0xffffffffu, p2, off);
    float pnorm_inv = rsqrtf(p2);

    for (int nn = half * 32 + warp; nn < n; nn += 64) {
        int node = b * n + nn;
        float di = dinv[node];
        float sc = di * di;
        float4 a = ((const float4*)(xw + (size_t)node * 128))[l];
        float4 ac0 = make_float4(a.x * sc, a.y * sc, a.z * sc, a.w * sc);
        float4 ac1 = make_float4(0.f, 0.f, 0.f, 0.f);
        float4 ac2 = make_float4(0.f, 0.f, 0.f, 0.f);
        float4 ac3 = make_float4(0.f, 0.f, 0.f, 0.f);
        int e0 = rowptr[node], e1 = rowend[node];
        int e = e0;
        for (; e + 4 <= e1; e += 4) {
            int s0 = esrc[e], s1 = esrc[e + 1], s2 = esrc[e + 2], s3 = esrc[e + 3];
            float c0 = ecoef[e], c1 = ecoef[e + 1], c2 = ecoef[e + 2], c3 = ecoef[e + 3];
            float4 v0 = ((const float4*)(xw + (size_t)s0 * 128))[l];
            float4 v1 = ((const float4*)(xw + (size_t)s1 * 128))[l];
            float4 v2 = ((const float4*)(xw + (size_t)s2 * 128))[l];
            float4 v3 = ((const float4*)(xw + (size_t)s3 * 128))[l];
            ac0.x = fmaf(c0, v0.x, ac0.x); ac0.y = fmaf(c0, v0.y, ac0.y);
            ac0.z = fmaf(c0, v0.z, ac0.z); ac0.w = fmaf(c0, v0.w, ac0.w);
            ac1.x = fmaf(c1, v1.x, ac1.x); ac1.y = fmaf(c1, v1.y, ac1.y);
            ac1.z = fmaf(c1, v1.z, ac1.z); ac1.w = fmaf(c1, v1.w, ac1.w);
            ac2.x = fmaf(c2, v2.x, ac2.x); ac2.y = fmaf(c2, v2.y, ac2.y);
            ac2.z = fmaf(c2, v2.z, ac2.z); ac2.w = fmaf(c2, v2.w, ac2.w);
            ac3.x = fmaf(c3, v3.x, ac3.x); ac3.y = fmaf(c3, v3.y, ac3.y);
            ac3.z = fmaf(c3, v3.z, ac3.z); ac3.w = fmaf(c3, v3.w, ac3.w);
        }
        for (; e < e1; e++) {
            int s = esrc[e];
            float c = ecoef[e];
            float4 v = ((const float4*)(xw + (size_t)s * 128))[l];
            ac0.x = fmaf(c, v.x, ac0.x); ac0.y = fmaf(c, v.y, ac0.y);
            ac0.z = fmaf(c, v.z, ac0.z); ac0.w = fmaf(c, v.w, ac0.w);
        }
        ac0.x += ac1.x + ac2.x + ac3.x;
        ac0.y += ac1.y + ac2.y + ac3.y;
        ac0.z += ac1.z + ac2.z + ac3.z;
        ac0.w += ac1.w + ac2.w + ac3.w;
        float4 o;
        o.x = fmaxf((ac0.x + bb.x - m.x) * bnscale.x + be.x, 0.f);
        o.y = fmaxf((ac0.y + bb.y - m.y) * bnscale.y + be.y, 0.f);
        o.z = fmaxf((ac0.z + bb.z - m.z) * bnscale.z + be.z, 0.f);
        o.w = fmaxf((ac0.w + bb.w - m.w) * bnscale.w + be.w, 0.f);
        ((float4*)(hc + (size_t)node * 128))[l] = o;
        float dot = o.x * p.x + o.y * p.y + o.z * p.z + o.w * p.w;
#pragma unroll
        for (int off = 16; off; off >>= 1) dot += __shfl_xor_sync(0xffffffffu, dot, off);
        if (l == 0) score[node] = tanhf(dot * pnorm_inv);
    }
}

// bitonic sort (SL = 512 or 1024 elements) + inv map + export sorted top-k
__global__ __launch_bounds__(1024)
void sort_inv(const float* __restrict__ score, float* __restrict__ svals,
              int* __restrict__ sidxg, int* __restrict__ inv, int n, int k, int SL)
{
    __shared__ float skey[1024];
    __shared__ int   sidx[1024];
    int b = blockIdx.x;
    int tid = threadIdx.x;

    if (tid < SL) {
        skey[tid] = (tid < n) ? score[b * n + tid] : -3.402823466e38f;
        sidx[tid] = tid;
    }
    __syncthreads();

    for (int kk = 2; kk <= SL; kk <<= 1) {
        for (int j = kk >> 1; j > 0; j >>= 1) {
            if (tid < (SL >> 1)) {
                int i = ((tid & ~(j - 1)) << 1) | (tid & (j - 1));
                int ixj = i | j;
                float ka = skey[i], kb = skey[ixj];
                int ia = sidx[i], ib = sidx[ixj];
                bool up = ((i & kk) == 0);
                bool sw = up ? ((ka < kb) || (ka == kb && ia > ib))
                             : ((ka > kb) || (ka == kb && ia < ib));
                if (sw) { skey[i] = kb; skey[ixj] = ka; sidx[i] = ib; sidx[ixj] = ia; }
            }
            __syncthreads();
        }
    }

    if (tid < n) inv[b * n + tid] = -1;
    __syncthreads();
    if (tid < k) {
        inv[b * n + sidx[tid]] = tid;
        svals[b * 1024 + tid] = skey[tid];
        sidxg[b * 1024 + tid] = sidx[tid];
    }
}

// pool: gather selected hc rows, scale, bf16 hi/lo split + mean/max flats
__global__ __launch_bounds__(1024)
void pool_kernel(const float* __restrict__ hc, const float* __restrict__ svals,
                 const int* __restrict__ sidxg,
                 bf16* __restrict__ hhi, bf16* __restrict__ hlo,
                 float* __restrict__ flats, int n, int k, int accum)
{
    __shared__ float4 ssum[32][32];
    __shared__ float4 smax[32][32];
    int b = blockIdx.x;
    int tid = threadIdx.x;
    int w = tid >> 5, l = tid & 31;

    float4 sum = make_float4(0.f, 0.f, 0.f, 0.f);
    float4 mx  = make_float4(-3.402823466e38f, -3.402823466e38f, -3.402823466e38f, -3.402823466e38f);
    for (int j = w; j < k; j += 32) {
        int p = b * n + sidxg[b * 1024 + j];
        float v = svals[b * 1024 + j];
        float4 hv = ((const float4*)(hc + (size_t)p * 128))[l];
        hv.x *= v; hv.y *= v; hv.z *= v; hv.w *= v;
        bf16 a0 = __float2bfloat16(hv.x), a1 = __float2bfloat16(hv.y);
        bf16 a2 = __float2bfloat16(hv.z), a3 = __float2bfloat16(hv.w);
        bf16 b0 = __float2bfloat16(hv.x - __bfloat162float(a0));
        bf16 b1 = __float2bfloat16(hv.y - __bfloat162float(a1));
        bf16 b2 = __float2bfloat16(hv.z - __bfloat162float(a2));
        bf16 b3 = __float2bfloat16(hv.w - __bfloat162float(a3));
        size_t rbase = (size_t)(b * k + j) * 128 + l * 4;
        *(ull*)(hhi + rbase) = pack4bf(a0, a1, a2, a3);
        *(ull*)(hlo + rbase) = pack4bf(b0, b1, b2, b3);
        sum.x += hv.x; sum.y += hv.y; sum.z += hv.z; sum.w += hv.w;
        mx.x = fmaxf(mx.x, hv.x); mx.y = fmaxf(mx.y, hv.y);
        mx.z = fmaxf(mx.z, hv.z); mx.w = fmaxf(mx.w, hv.w);
    }
    ssum[w][l] = sum; smax[w][l] = mx;
    __syncthreads();
    if (w == 0) {
#pragma unroll
        for (int q = 1; q < 32; q++) {
            float4 s2 = ssum[q][l], m2 = smax[q][l];
            sum.x += s2.x; sum.y += s2.y; sum.z += s2.z; sum.w += s2.w;
            mx.x = fmaxf(mx.x, m2.x); mx.y = fmaxf(mx.y, m2.y);
            mx.z = fmaxf(mx.z, m2.z); mx.w = fmaxf(mx.w, m2.w);
        }
        float kin = (float)k;
        float* f1 = flats + b * 256 + l * 4;
        float* f2 = flats + b * 256 + 128 + l * 4;
        if (accum) {
            f1[0] += sum.x / kin; f1[1] += sum.y / kin; f1[2] += sum.z / kin; f1[3] += sum.w / kin;
            f2[0] += mx.x; f2[1] += mx.y; f2[2] += mx.z; f2[3] += mx.w;
        } else {
            f1[0] = sum.x / kin; f1[1] = sum.y / kin; f1[2] = sum.z / kin; f1[3] = sum.w / kin;
            f2[0] = mx.x; f2[1] = mx.y; f2[2] = mx.z; f2[3] = mx.w;
        }
    }
}

__global__ __launch_bounds__(512)
void mlp_kernel(const float* __restrict__ flats, const float* __restrict__ d1w,
                const float* __restrict__ d1b, const float* __restrict__ d2w,
                const float* __restrict__ d2b, float* __restrict__ out)
{
    __shared__ float f[256];
    __shared__ float hd[512];
    int b = blockIdx.x, t = threadIdx.x;
    if (t < 256) f[t] = flats[b * 256 + t];
    __syncthreads();
    float acc = d1b[t];
#pragma unroll 8
    for (int i = 0; i < 256; i++) acc = fmaf(f[i], d1w[i * 512 + t], acc);
    hd[t] = fmaxf(acc, 0.f);
    __syncthreads();
    if (t < CC) {
        float o = d2b[t];
#pragma unroll 8
        for (int i = 0; i < 512; i++) o = fmaf(hd[i], d2w[i * CC + t], o);
        out[b * CC + t] = o;
    }
}

// ---------------- host launcher ----------------
extern "C" void kernel_launch(void* const* d_in, const int* in_sizes, int n_in,
                              void* d_out, int out_size)
{
    const float* x       = (const float*)d_in[0];
    const int*   ei      = (const int*)d_in[1];
    const float* ew      = (const float*)d_in[3];
    const float* conv1_w = (const float*)d_in[4];
    const float* conv_w  = (const float*)d_in[5];
    const float* conv_b  = (const float*)d_in[6];
    const float* bn_g    = (const float*)d_in[7];
    const float* bn_be   = (const float*)d_in[8];
    const float* bn_m    = (const float*)d_in[9];
    const float* bn_v    = (const float*)d_in[10];
    const float* pool_w  = (const float*)d_in[11];
    const float* d1w     = (const float*)d_in[12];
    const float* d1b     = (const float*)d_in[13];
    const float* d2w     = (const float*)d_in[14];
    const float* d2b     = (const float*)d_in[15];
    int E = in_sizes[3];

    float *xw, *hc, *score, *sval, *ecoef, *flats, *dinv;
    float *weE[2];
    int *rowptr, *rowend, *esrc, *inv, *gcnt, *sidxg;
    int *srcE[2], *dstE[2];
    bf16 *xhi, *xlo, *hhi, *hlo, *whi, *wlo;
    cudaGetSymbolAddress((void**)&xw,     g_xw);
    cudaGetSymbolAddress((void**)&hc,     g_hc);
    cudaGetSymbolAddress((void**)&score,  g_score);
    cudaGetSymbolAddress((void**)&sval,   g_sval);
    cudaGetSymbolAddress((void**)&sidxg,  g_sidx);
    cudaGetSymbolAddress((void**)&rowptr, g_rowptr);
    cudaGetSymbolAddress((void**)&rowend, g_rowend);
    cudaGetSymbolAddress((void**)&esrc,   g_esrc);
    cudaGetSymbolAddress((void**)&ecoef,  g_ecoef);
    cudaGetSymbolAddress((void**)&flats,  g_flats);
    cudaGetSymbolAddress((void**)&dinv,   g_dinv);
    cudaGetSymbolAddress((void**)&inv,    g_inv);
    cudaGetSymbolAddress((void**)&gcnt,   g_gcnt);
    cudaGetSymbolAddress((void**)&xhi,    g_xhi);
    cudaGetSymbolAddress((void**)&xlo,    g_xlo);
    cudaGetSymbolAddress((void**)&hhi,    g_hhi);
    cudaGetSymbolAddress((void**)&hlo,    g_hlo);
    cudaGetSymbolAddress((void**)&whi,    g_whi);
    cudaGetSymbolAddress((void**)&wlo,    g_wlo);
    {
        float* p; int* q;
        cudaGetSymbolAddress((void**)&q, g_srcE);   srcE[0] = q; srcE[1] = q + EMAX;
        cudaGetSymbolAddress((void**)&q, g_dstE);   dstE[0] = q; dstE[1] = q + EMAX;
        cudaGetSymbolAddress((void**)&p, g_weE);    weE[0]  = p; weE[1]  = p + EMAX;
    }

    const int ns[6] = {1000, 800, 640, 512, 410, 328};
    const int ks[6] = {800, 640, 512, 410, 328, 263};
    const int sl[6] = {1024, 1024, 1024, 512, 512, 512};
    const int SMEM_G64  = 4 * 128 * 64 * 2;    // 65536
    const int SMEM_G128 = 4 * 128 * 128 * 2;   // 131072

    cudaFuncSetAttribute(gemm_bf16<64>,  cudaFuncAttributeMaxDynamicSharedMemorySize, SMEM_G64);
    cudaFuncSetAttribute(gemm_bf16<128>, cudaFuncAttributeMaxDynamicSharedMemorySize, SMEM_G128);

    // static stream + event pool: created ONCE, reused every call (no per-call allocation)
    static cudaStream_t s1 = 0;
    static cudaEvent_t evp[16];
    static int inited = 0;
    if (!inited) {
        cudaStreamCreateWithFlags(&s1, cudaStreamNonBlocking);
        for (int i = 0; i < 16; i++)
            cudaEventCreateWithFlags(&evp[i], cudaEventDisableTiming);
        inited = 1;
    }
    cudaStream_t s0 = (cudaStream_t)0;
    int evc = 0;

    #define FORK_S1() do { cudaEvent_t e_ = evp[evc++]; \
        cudaEventRecord(e_, s0); cudaStreamWaitEvent(s1, e_, 0); } while (0)
    #define JOIN_S0() do { cudaEvent_t e_ = evp[evc++]; \
        cudaEventRecord(e_, s1); cudaStreamWaitEvent(s0, e_, 0); } while (0)

    // ---- prologue: edge build (layer0) on s0 ∥ prep + gemm0 on s1 ----
    FORK_S1();
    w_prep<<<(6 * 16384 + 255) / 256, 256, 0, s1>>>(conv1_w, conv_w, whi, wlo);
    x_prep<<<(NMAX * 64 + 255) / 256, 256, 0, s1>>>(x, xhi, xlo, NMAX * 64);
    gemm_bf16<64><<<BB * ns[0] / 128, 256, SMEM_G64, s1>>>(xhi, xlo, whi, wlo, xw);

    edge_build<<<BB, 1024, 0, s0>>>(ei, ei + E, ew, SEG, 0, 1000, 0, ns[0], (const int*)0,
                                    srcE[0], dstE[0], weE[0], esrc, ecoef,
                                    dinv, rowptr, rowend, gcnt);
    JOIN_S0();

    for (int i = 0; i < 6; i++) {
        int n = ns[i], k = ks[i];
        int cur = i & 1, nxt = cur ^ 1;

        gcn_gather<<<2 * BB, 1024, 0, s0>>>(xw, rowptr, rowend, esrc, ecoef, dinv,
                                            conv_b + i * 128, bn_g + i * 128, bn_be + i * 128,
                                            bn_m + i * 128, bn_v + i * 128, pool_w + i * 128,
                                            hc, score, n);

        sort_inv<<<BB, 1024, 0, s0>>>(score, sval, sidxg, inv, n, k, sl[i]);

        if (i < 5) {
            // edge_build(i+1) depends only on inv — overlap with pool + gemm(i+1)
            FORK_S1();
            edge_build<<<BB, 1024, 0, s1>>>(srcE[cur], dstE[cur], weE[cur], 0, 1, 0,
                                            n, ns[i + 1], inv,
                                            srcE[nxt], dstE[nxt], weE[nxt], esrc, ecoef,
                                            dinv, rowptr, rowend, gcnt);
        }

        pool_kernel<<<BB, 1024, 0, s0>>>(hc, sval, sidxg, hhi, hlo, flats, n, k, i > 0);

        if (i < 5) {
            gemm_bf16<128><<<BB * k / 128, 256, SMEM_G128, s0>>>(hhi, hlo,
                whi + (size_t)(i + 1) * 16384, wlo + (size_t)(i + 1) * 16384, xw);
            JOIN_S0();   // wait for edge_build(i+1)
        }
    }

    mlp_kernel<<<BB, 512, 0, s0>>>(flats, d1w, d1b, d2w, d2b, (float*)d_out);

    #undef FORK_S1
    #undef JOIN_S0
}